// round 15
// baseline (speedup 1.0000x reference)
#include <cuda_runtime.h>
#include <cuda_fp16.h>
#include <math.h>

#define N_NODES 50000
#define N_EDGES 800000
#define IN_DIM 50
#define HID 64
#define HEADS 4
#define NLAYERS 3
#define NC 12
#define INV_SQRT_C 0.25f
#define LN_EPS 1e-5f
#define SCAN_BLK ((N_NODES + 1023) / 1024)   // 49
#define NTILES ((N_NODES + 63) / 64)         // 782
#define G4_BLOCKS ((NTILES + 3) / 4)         // 196 (4 tiles per block)
#define PREPW_BLK ((13 * 4096 + 255) / 256)  // 208
#define HIST_BLK ((N_EDGES + 255) / 256)     // 3125
#define SCAT_BLK ((N_EDGES + 511) / 512)     // 1563

typedef unsigned long long ull;

__device__ __forceinline__ ull ff2(ull a, ull b, ull c) {
    ull d;
    asm("fma.rn.f32x2 %0, %1, %2, %3;" : "=l"(d) : "l"(a), "l"(b), "l"(c));
    return d;
}
__device__ __forceinline__ ull packf2(float lo, float hi) {
    return ((ull)__float_as_uint(hi) << 32) | (ull)__float_as_uint(lo);
}
__device__ __forceinline__ float sum2(ull v) {
    return __uint_as_float((unsigned)(v & 0xffffffffu)) + __uint_as_float((unsigned)(v >> 32));
}

// ---------------- scratch ----------------------------------------------------
__device__ __align__(16) float  g_h[N_NODES * HID];
__device__ __align__(16) __half g_hh[N_NODES * HID];
__device__ __align__(16) float  g_q[N_NODES * HID];
__device__ __align__(16) float  g_skip[N_NODES * HID];
// interleaved kv: per node, lane L (0..31) owns halves {k[2L],k[2L+1],v[2L],v[2L+1]}
__device__ __align__(16) __half g_kv[N_NODES * 128];
__device__ __align__(16) __half g_wt[13 * 64 * 72];
__device__ int   g_cnt[N_NODES];
__device__ int   g_rowptr[N_NODES + 1];
__device__ int   g_fill[N_NODES];
__device__ ull   g_edge[N_EDGES];                      // (ea<<32 | src)
__device__ int   g_psum[64];
__device__ int   g_scan_ctr;

// ================= device bodies =============================================

__device__ __forceinline__ void ingemm_body(int bid, int t,
                         const float* __restrict__ x,
                         const float* __restrict__ Win,
                         const float* __restrict__ b_in,
                         float* xs) {
    int c = t & 63, rg = t >> 6;
    ull w2[26];
    #pragma unroll
    for (int k = 0; k < 25; k++)
        w2[k] = packf2(Win[(2 * k) * HID + c], Win[(2 * k + 1) * HID + c]);
    w2[25] = 0ull;
    int n0 = bid * 64;
    for (int idx = t; idx < 64 * IN_DIM; idx += 256) {
        int r = idx / IN_DIM, k = idx % IN_DIM;
        int row = n0 + r;
        xs[r * 52 + k] = (row < N_NODES) ? x[row * IN_DIM + k] : 0.f;
    }
    if (rg == 0) { xs[c * 52 + 50] = 0.f; xs[c * 52 + 51] = 0.f; }
    __syncthreads();
    float bias = b_in[c];
    int rend = min(rg * 16 + 16, N_NODES - n0);
    for (int r = rg * 16; r < rend; r++) {
        const ulonglong2* hr = (const ulonglong2*)&xs[r * 52];
        ull acc_a = packf2(bias, 0.f), acc_b = 0ull;
        #pragma unroll
        for (int kk = 0; kk < 13; kk++) {
            ulonglong2 hv = hr[kk];
            acc_a = ff2(w2[2 * kk + 0], hv.x, acc_a);
            acc_b = ff2(w2[2 * kk + 1], hv.y, acc_b);
        }
        float acc = sum2(acc_a) + sum2(acc_b);
        g_h[(n0 + r) * HID + c] = acc;
        g_hh[(n0 + r) * HID + c] = __float2half_rn(acc);
    }
}

__device__ __forceinline__ void prepw_body(int id,
                         const float* __restrict__ Wq, const float* __restrict__ Wk,
                         const float* __restrict__ Wv, const float* __restrict__ Wsk,
                         const float* __restrict__ Wc1) {
    if (id >= 13 * 4096) return;
    int k = id & 63, n = (id >> 6) & 63, m = id >> 12;
    const float* W;
    float scal = 1.f;
    if (m == 12) W = Wc1;
    else {
        int li = m >> 2, mat = m & 3;
        if (mat == 0)      { W = Wq + li * 4096; scal = INV_SQRT_C; }
        else if (mat == 1) W = Wk  + li * 4096;
        else if (mat == 2) W = Wv  + li * 4096;
        else               W = Wsk + li * 4096;
    }
    g_wt[(m * 64 + n) * 72 + k] = __float2half_rn(W[k * 64 + n] * scal);
}

__device__ __forceinline__ void gemm4_body(int li, int t, int tile_start, int tile_stride,
                        const float* __restrict__ bq, const float* __restrict__ bk,
                        const float* __restrict__ bv, const float* __restrict__ bsk) {
    __shared__ __half As[64][72];
    __shared__ __half Bs[4][64][72];
    __shared__ float  bias_s[4][64];

    int w = t >> 5, lane = t & 31;
    int mat = w & 3, rg = w >> 2;

    const float* b;
    if (mat == 0)      b = bq  + li * 64;
    else if (mat == 1) b = bk  + li * 64;
    else if (mat == 2) b = bv  + li * 64;
    else               b = bsk + li * 64;
    float scal = (mat == 0) ? INV_SQRT_C : 1.f;

    {
        const uint4* src = (const uint4*)(g_wt + (li * 4 + mat) * 64 * 72);
        uint4* dst = (uint4*)&Bs[mat][0][0];
        for (int idx = rg * 32 + lane; idx < 576; idx += 128)
            dst[idx] = src[idx];
        if (rg == 0)
            for (int c = lane; c < 64; c += 32) bias_s[mat][c] = b[c] * scal;
    }

    int g = lane >> 2, tig = lane & 3;
    int r0 = rg * 16;
    int arow = t >> 3, acol = (t & 7) * 8;

    for (int tile = tile_start; tile < NTILES; tile += tile_stride) {
        int n0 = tile * 64;
        __syncthreads();
        {
            int row = n0 + arow;
            uint4 v = make_uint4(0u, 0u, 0u, 0u);
            if (row < N_NODES) v = *(const uint4*)&g_hh[row * 64 + acol];
            *(uint4*)&As[arow][acol] = v;
        }
        __syncthreads();

        unsigned afr[4][4];
        #pragma unroll
        for (int ks = 0; ks < 4; ks++) {
            int k0 = ks * 16;
            afr[ks][0] = *(const unsigned*)&As[r0 + g][k0 + 2 * tig];
            afr[ks][1] = *(const unsigned*)&As[r0 + g + 8][k0 + 2 * tig];
            afr[ks][2] = *(const unsigned*)&As[r0 + g][k0 + 2 * tig + 8];
            afr[ks][3] = *(const unsigned*)&As[r0 + g + 8][k0 + 2 * tig + 8];
        }

        int row0 = n0 + r0 + g;
        int row1 = row0 + 8;

        #pragma unroll
        for (int nt = 0; nt < 8; nt++) {
            int col = nt * 8 + 2 * tig;
            float c0 = bias_s[mat][col], c1 = bias_s[mat][col + 1];
            float c2 = c0, c3 = c1;
            #pragma unroll
            for (int ks = 0; ks < 4; ks++) {
                unsigned b0 = *(const unsigned*)&Bs[mat][nt * 8 + g][ks * 16 + 2 * tig];
                unsigned b1 = *(const unsigned*)&Bs[mat][nt * 8 + g][ks * 16 + 2 * tig + 8];
                asm volatile(
                    "mma.sync.aligned.m16n8k16.row.col.f32.f16.f16.f32 "
                    "{%0,%1,%2,%3}, {%4,%5,%6,%7}, {%8,%9}, {%0,%1,%2,%3};"
                    : "+f"(c0), "+f"(c1), "+f"(c2), "+f"(c3)
                    : "r"(afr[ks][0]), "r"(afr[ks][1]), "r"(afr[ks][2]), "r"(afr[ks][3]),
                      "r"(b0), "r"(b1));
            }
            if (mat == 0) {
                if (row0 < N_NODES) *(float2*)&g_q[row0 * 64 + col] = make_float2(c0, c1);
                if (row1 < N_NODES) *(float2*)&g_q[row1 * 64 + col] = make_float2(c2, c3);
            } else if (mat == 3) {
                if (row0 < N_NODES) *(float2*)&g_skip[row0 * 64 + col] = make_float2(c0, c1);
                if (row1 < N_NODES) *(float2*)&g_skip[row1 * 64 + col] = make_float2(c2, c3);
            } else {
                int pos = ((col >> 1) << 2) + ((mat == 2) ? 2 : 0);
                if (row0 < N_NODES) *(__half2*)&g_kv[row0 * 128 + pos] = __floats2half2_rn(c0, c1);
                if (row1 < N_NODES) *(__half2*)&g_kv[row1 * 128 + pos] = __floats2half2_rn(c2, c3);
            }
        }
    }
}

__device__ __forceinline__ void scatter_body(int e, const int* __restrict__ ei,
                                             const float* __restrict__ ea) {
    if (e < N_EDGES) {
        int dst = ei[N_EDGES + e];
        int base = g_rowptr[dst] + g_psum[dst >> 10];
        int pos = base + atomicAdd(&g_fill[dst], 1);
        g_edge[pos] = ((ull)__float_as_uint(ea[e]) << 32) | (unsigned)ei[e];
    }
}

// ================= kernels ===================================================

__global__ __launch_bounds__(256) void k_fused1(
        const float* __restrict__ x, const float* __restrict__ Win,
        const float* __restrict__ b_in,
        const float* __restrict__ Wq, const float* __restrict__ Wk,
        const float* __restrict__ Wv, const float* __restrict__ Wsk,
        const float* __restrict__ Wc1,
        const int* __restrict__ ei) {
    __shared__ __align__(16) float xs[64 * 52];
    int b = blockIdx.x, t = threadIdx.x;
    if (b < NTILES) {
        ingemm_body(b, t, x, Win, b_in, xs);
    } else if (b < NTILES + PREPW_BLK) {
        prepw_body((b - NTILES) * 256 + t, Wq, Wk, Wv, Wsk, Wc1);
    } else {
        int e = (b - NTILES - PREPW_BLK) * 256 + t;
        if (e < N_NODES) g_fill[e] = 0;
        if (e < N_EDGES) atomicAdd(&g_cnt[ei[N_EDGES + e]], 1);
    }
}

__global__ void k_scan() {
    __shared__ int wsum[32];
    __shared__ int s_last;
    __shared__ int w0tot;
    int t = threadIdx.x, lane = t & 31, wid = t >> 5;
    int i = blockIdx.x * 1024 + t;
    int v = (i < N_NODES) ? g_cnt[i] : 0;
    if (i < N_NODES) g_cnt[i] = 0;
    int incl = v;
    #pragma unroll
    for (int o = 1; o < 32; o <<= 1) {
        int u = __shfl_up_sync(0xffffffffu, incl, o);
        if (lane >= o) incl += u;
    }
    if (lane == 31) wsum[wid] = incl;
    __syncthreads();
    if (wid == 0) {
        int ws = wsum[lane];
        int wincl = ws;
        #pragma unroll
        for (int o = 1; o < 32; o <<= 1) {
            int u = __shfl_up_sync(0xffffffffu, wincl, o);
            if (lane >= o) wincl += u;
        }
        wsum[lane] = wincl - ws;
        if (lane == 31) g_psum[blockIdx.x] = wincl;
    }
    __syncthreads();
    int excl = incl - v + wsum[wid];
    if (i < N_NODES) g_rowptr[i] = excl;

    __threadfence();
    if (t == 0) s_last = (atomicAdd(&g_scan_ctr, 1) == SCAN_BLK - 1) ? 1 : 0;
    __syncthreads();
    if (s_last) {
        int v2 = (t < SCAN_BLK) ? *((volatile int*)g_psum + t) : 0;
        int incl2 = v2;
        if (t < 64) {
            #pragma unroll
            for (int o = 1; o < 32; o <<= 1) {
                int u = __shfl_up_sync(0xffffffffu, incl2, o);
                if (lane >= o) incl2 += u;
            }
            if (t == 31) w0tot = incl2;
        }
        __syncthreads();
        if (t < 64) {
            int excl2 = incl2 - v2 + ((t >= 32) ? w0tot : 0);
            if (t < SCAN_BLK) g_psum[t] = excl2;
            if (t == SCAN_BLK - 1) g_rowptr[N_NODES] = v2;
        }
        if (t == 0) g_scan_ctr = 0;
    }
}

__global__ __launch_bounds__(512) void k_gemm4sc(int li,
                        const float* __restrict__ bq, const float* __restrict__ bk,
                        const float* __restrict__ bv, const float* __restrict__ bsk,
                        const int* __restrict__ ei, const float* __restrict__ ea) {
    if (blockIdx.x < G4_BLOCKS) {
        gemm4_body(li, threadIdx.x, blockIdx.x, G4_BLOCKS, bq, bk, bv, bsk);
    } else {
        int e = (blockIdx.x - G4_BLOCKS) * 512 + threadIdx.x;
        scatter_body(e, ei, ea);
    }
}

__global__ __launch_bounds__(512) void k_gemm4(int li,
                        const float* __restrict__ bq, const float* __restrict__ bk,
                        const float* __restrict__ bv, const float* __restrict__ bsk) {
    gemm4_body(li, threadIdx.x, blockIdx.x, G4_BLOCKS, bq, bk, bv, bsk);
}

// ---------------- fused node kernel: warp/node, 64-thr blocks, depth-6 pipe --
#define LDKV(E) __ldg((const uint2*)g_kv + (((E) & 0xffffffffu) * 32 + lane))
#define NODE_BODY(E, R) { \
    float w_ = __uint_as_float((unsigned)((E) >> 32)); \
    float2 kf_ = __half22float2(*(const __half2*)&(R).x); \
    float2 vf_ = __half22float2(*(const __half2*)&(R).y); \
    float p_ = q2.x * kf_.x + q2.y * kf_.y; \
    p_ += __shfl_xor_sync(0xffffffffu, p_, 1, 8); \
    p_ += __shfl_xor_sync(0xffffffffu, p_, 2, 8); \
    p_ += __shfl_xor_sync(0xffffffffu, p_, 4, 8); \
    float ex_ = __expf(fmaf(w_, qwe, p_)); \
    d += ex_; spw = fmaf(ex_, w_, spw); \
    accx = fmaf(ex_, vf_.x, accx); accy = fmaf(ex_, vf_.y, accy); \
}

__global__ __launch_bounds__(64) void k_node3(int li,
                        const float* __restrict__ Wedge,
                        const float* __restrict__ Wbeta,
                        const float* __restrict__ lng,
                        const float* __restrict__ lnb) {
    int n = blockIdx.x * 2 + (threadIdx.x >> 5);
    if (n >= N_NODES) return;
    int lane = threadIdx.x & 31;

    float2 q2  = ((const float2*)g_q)[n * 32 + lane];     // pre-scaled
    float2 we2 = ((const float2*)Wedge)[li * 32 + lane];

    float pw = q2.x * we2.x + q2.y * we2.y;
    pw += __shfl_xor_sync(0xffffffffu, pw, 1, 8);
    pw += __shfl_xor_sync(0xffffffffu, pw, 2, 8);
    pw += __shfl_xor_sync(0xffffffffu, pw, 4, 8);
    float qwe = pw;

    int j0 = g_rowptr[n] + g_psum[n >> 10];
    int j1 = g_rowptr[n + 1] + g_psum[(n + 1) >> 10];
    int cnt = j1 - j0;
    const ull* ep = g_edge + j0;

    float d = 0.f, spw = 0.f, accx = 0.f, accy = 0.f;

    ull e0 = 0, e1 = 0, e2 = 0, e3 = 0, e4 = 0, e5 = 0;
    uint2 r0 = make_uint2(0u,0u), r1 = r0, r2 = r0, r3 = r0, r4 = r0, r5 = r0;
    if (cnt > 0) { e0 = __ldg(ep + 0); r0 = LDKV(e0); }
    if (cnt > 1) { e1 = __ldg(ep + 1); r1 = LDKV(e1); }
    if (cnt > 2) { e2 = __ldg(ep + 2); r2 = LDKV(e2); }
    if (cnt > 3) { e3 = __ldg(ep + 3); r3 = LDKV(e3); }
    if (cnt > 4) { e4 = __ldg(ep + 4); r4 = LDKV(e4); }
    if (cnt > 5) { e5 = __ldg(ep + 5); r5 = LDKV(e5); }

    int j = 0;
    for (; j + 12 <= cnt; j += 6) {
        NODE_BODY(e0, r0); e0 = __ldg(ep + j + 6);  r0 = LDKV(e0);
        NODE_BODY(e1, r1); e1 = __ldg(ep + j + 7);  r1 = LDKV(e1);
        NODE_BODY(e2, r2); e2 = __ldg(ep + j + 8);  r2 = LDKV(e2);
        NODE_BODY(e3, r3); e3 = __ldg(ep + j + 9);  r3 = LDKV(e3);
        NODE_BODY(e4, r4); e4 = __ldg(ep + j + 10); r4 = LDKV(e4);
        NODE_BODY(e5, r5); e5 = __ldg(ep + j + 11); r5 = LDKV(e5);
    }
    int left = cnt - j;           // 0..11
    if (left > 0) NODE_BODY(e0, r0);
    if (left > 1) NODE_BODY(e1, r1);
    if (left > 2) NODE_BODY(e2, r2);
    if (left > 3) NODE_BODY(e3, r3);
    if (left > 4) NODE_BODY(e4, r4);
    if (left > 5) NODE_BODY(e5, r5);
    for (int jj = j + 6; jj < cnt; jj++) {
        ull e = __ldg(ep + jj); uint2 r = LDKV(e);
        NODE_BODY(e, r);
    }

    float inv = 1.f / (d + 1e-16f);
    float ox = (accx + we2.x * spw) * inv;
    float oy = (accy + we2.y * spw) * inv;

    float2 xr = ((const float2*)g_skip)[n * 32 + lane];
    const float2* Wb = (const float2*)(Wbeta + li * 192);
    float2 w1 = Wb[lane], w2 = Wb[32 + lane], w3 = Wb[64 + lane];
    float contrib = ox * w1.x + oy * w1.y + xr.x * w2.x + xr.y * w2.y
                  + (ox - xr.x) * w3.x + (oy - xr.y) * w3.y;
    #pragma unroll
    for (int o = 16; o >= 1; o >>= 1)
        contrib += __shfl_xor_sync(0xffffffffu, contrib, o);
    float beta = 1.f / (1.f + __expf(-contrib));

    float2 hres = ((const float2*)g_h)[n * 32 + lane];
    float zx = fmaf(beta, xr.x - ox, ox) + hres.x;
    float zy = fmaf(beta, xr.y - oy, oy) + hres.y;

    float s1 = zx + zy;
    float s2 = zx * zx + zy * zy;
    #pragma unroll
    for (int o = 16; o >= 1; o >>= 1) {
        s1 += __shfl_xor_sync(0xffffffffu, s1, o);
        s2 += __shfl_xor_sync(0xffffffffu, s2, o);
    }
    float mu  = s1 * (1.f / 64.f);
    float var = s2 * (1.f / 64.f) - mu * mu;
    float rstd = rsqrtf(var + LN_EPS);
    float2 g = ((const float2*)lng)[li * 32 + lane];
    float2 b = ((const float2*)lnb)[li * 32 + lane];
    float hx = (zx - mu) * rstd * g.x + b.x;
    float hy = (zy - mu) * rstd * g.y + b.y;
    ((float2*)g_h)[n * 32 + lane] = make_float2(hx, hy);
    __half2 hh = __floats2half2_rn(hx, hy);
    ((unsigned*)g_hh)[n * 32 + lane] = *(unsigned*)&hh;
}

// ---------------- head: stage1 HMMA + stage2 FFMA2 ---------------------------
__global__ __launch_bounds__(256) void k_final(const float* __restrict__ bc1,
                        const float* __restrict__ Wc2, const float* __restrict__ bc2,
                        float* __restrict__ out) {
    __shared__ __half As[64][72];
    __shared__ __half Bs[64][72];
    __shared__ __align__(16) float h1s[64 * 64];
    __shared__ float bias1[64];

    int t = threadIdx.x;
    int w = t >> 5, lane = t & 31;
    int n0 = blockIdx.x * 64;

    for (int idx = t; idx < 512; idx += 256) {
        int row = n0 + (idx >> 3), col = (idx & 7) * 8;
        uint4 v = make_uint4(0u, 0u, 0u, 0u);
        if (row < N_NODES) v = *(const uint4*)&g_hh[row * 64 + col];
        *(uint4*)&As[idx >> 3][col] = v;
    }
    {
        const uint4* src = (const uint4*)(g_wt + 12 * 64 * 72);
        uint4* dst = (uint4*)&Bs[0][0];
        for (int idx = t; idx < 576; idx += 256) dst[idx] = src[idx];
    }
    if (t < 64) bias1[t] = bc1[t];
    __syncthreads();

    {
        int rg = w & 3, nh = w >> 2;
        int g = lane >> 2, tig = lane & 3;
        int r0 = rg * 16;
        unsigned afr[4][4];
        #pragma unroll
        for (int ks = 0; ks < 4; ks++) {
            int k0 = ks * 16;
            afr[ks][0] = *(const unsigned*)&As[r0 + g][k0 + 2 * tig];
            afr[ks][1] = *(const unsigned*)&As[r0 + g + 8][k0 + 2 * tig];
            afr[ks][2] = *(const unsigned*)&As[r0 + g][k0 + 2 * tig + 8];
            afr[ks][3] = *(const unsigned*)&As[r0 + g + 8][k0 + 2 * tig + 8];
        }
        #pragma unroll
        for (int q = 0; q < 4; q++) {
            int nt = nh * 4 + q;
            int col = nt * 8 + 2 * tig;
            float c0 = bias1[col], c1 = bias1[col + 1];
            float c2 = c0, c3 = c1;
            #pragma unroll
            for (int ks = 0; ks < 4; ks++) {
                unsigned b0 = *(const unsigned*)&Bs[nt * 8 + g][ks * 16 + 2 * tig];
                unsigned b1 = *(const unsigned*)&Bs[nt * 8 + g][ks * 16 + 2 * tig + 8];
                asm volatile(
                    "mma.sync.aligned.m16n8k16.row.col.f32.f16.f16.f32 "
                    "{%0,%1,%2,%3}, {%4,%5,%6,%7}, {%8,%9}, {%0,%1,%2,%3};"
                    : "+f"(c0), "+f"(c1), "+f"(c2), "+f"(c3)
                    : "r"(afr[ks][0]), "r"(afr[ks][1]), "r"(afr[ks][2]), "r"(afr[ks][3]),
                      "r"(b0), "r"(b1));
            }
            *(float2*)&h1s[(r0 + g) * 64 + col]     = make_float2(fmaxf(c0, 0.f), fmaxf(c1, 0.f));
            *(float2*)&h1s[(r0 + g + 8) * 64 + col] = make_float2(fmaxf(c2, 0.f), fmaxf(c3, 0.f));
        }
    }
    __syncthreads();

    if (t < 240) {
        int c2 = t % 12, rg2 = t / 12;
        ull wr2[32];
        #pragma unroll
        for (int k = 0; k < 32; k++)
            wr2[k] = packf2(Wc2[(2 * k) * NC + c2], Wc2[(2 * k + 1) * NC + c2]);
        float b2 = bc2[c2];
        int rmax = min(64, N_NODES - n0);
        for (int r = rg2; r < rmax; r += 20) {
            const ulonglong2* hr = (const ulonglong2*)&h1s[r * 64];
            ull acc_a = packf2(b2, 0.f), acc_b = 0ull;
            #pragma unroll
            for (int kk = 0; kk < 16; kk++) {
                ulonglong2 hv = hr[kk];
                acc_a = ff2(wr2[2 * kk + 0], hv.x, acc_a);
                acc_b = ff2(wr2[2 * kk + 1], hv.y, acc_b);
            }
            out[(n0 + r) * NC + c2] = sum2(acc_a) + sum2(acc_b);
        }
    }
}

// ---------------- launch -----------------------------------------------------
extern "C" void kernel_launch(void* const* d_in, const int* in_sizes, int n_in,
                              void* d_out, int out_size) {
    const float* x     = (const float*)d_in[0];
    const int*   ei    = (const int*)  d_in[1];
    const float* ea    = (const float*)d_in[2];
    const float* Win   = (const float*)d_in[3];
    const float* b_in  = (const float*)d_in[4];
    const float* Wq    = (const float*)d_in[5];
    const float* bq    = (const float*)d_in[6];
    const float* Wk    = (const float*)d_in[7];
    const float* bk    = (const float*)d_in[8];
    const float* Wv    = (const float*)d_in[9];
    const float* bv    = (const float*)d_in[10];
    const float* Wedge = (const float*)d_in[11];
    const float* Wskip = (const float*)d_in[12];
    const float* bskip = (const float*)d_in[13];
    const float* Wbeta = (const float*)d_in[14];
    const float* ln_g  = (const float*)d_in[15];
    const float* ln_b  = (const float*)d_in[16];
    const float* Wc1   = (const float*)d_in[17];
    const float* bc1   = (const float*)d_in[18];
    const float* Wc2   = (const float*)d_in[19];
    const float* bc2   = (const float*)d_in[20];
    float* out = (float*)d_out;

    int nodeblk = (N_NODES + 1) / 2;     // 2 warps per block

    // launch #4 (ncu capture slot) = k_node3 layer 0
    k_fused1<<<NTILES + PREPW_BLK + HIST_BLK, 256>>>(x, Win, b_in,
                Wq, Wk, Wv, Wskip, Wc1, ei);                                // 1
    k_scan<<<SCAN_BLK, 1024>>>();                                           // 2
    k_gemm4sc<<<G4_BLOCKS + SCAT_BLK, 512>>>(0, bq, bk, bv, bskip, ei, ea); // 3
    k_node3<<<nodeblk, 64>>>(0, Wedge, Wbeta, ln_g, ln_b);                  // 4 (profiled)

    for (int li = 1; li < NLAYERS; li++) {
        k_gemm4<<<G4_BLOCKS, 512>>>(li, bq, bk, bv, bskip);
        k_node3<<<nodeblk, 64>>>(li, Wedge, Wbeta, ln_g, ln_b);
    }

    k_final<<<NTILES, 256>>>(bc1, Wc2, bc2, out);
}

// round 16
// speedup vs baseline: 1.0704x; 1.0704x over previous
#include <cuda_runtime.h>
#include <cuda_fp16.h>
#include <math.h>

#define N_NODES 50000
#define N_EDGES 800000
#define IN_DIM 50
#define HID 64
#define HEADS 4
#define NLAYERS 3
#define NC 12
#define INV_SQRT_C 0.25f
#define LOG2E 1.4426950408889634f
#define LN_EPS 1e-5f
#define SCAN_BLK ((N_NODES + 1023) / 1024)   // 49
#define NTILES ((N_NODES + 63) / 64)         // 782
#define G4_BLOCKS ((NTILES + 1) / 2)         // 391 (2 tiles per block)
#define PREPW_BLK ((13 * 4096 + 255) / 256)  // 208
#define HIST_BLK ((N_EDGES + 255) / 256)     // 3125
#define SCAT_BLK ((N_EDGES + 511) / 512)     // 1563

typedef unsigned long long ull;

__device__ __forceinline__ ull ff2(ull a, ull b, ull c) {
    ull d;
    asm("fma.rn.f32x2 %0, %1, %2, %3;" : "=l"(d) : "l"(a), "l"(b), "l"(c));
    return d;
}
__device__ __forceinline__ ull packf2(float lo, float hi) {
    return ((ull)__float_as_uint(hi) << 32) | (ull)__float_as_uint(lo);
}
__device__ __forceinline__ float sum2(ull v) {
    return __uint_as_float((unsigned)(v & 0xffffffffu)) + __uint_as_float((unsigned)(v >> 32));
}

// ---------------- scratch ----------------------------------------------------
__device__ __align__(16) float  g_h[N_NODES * HID];
__device__ __align__(16) __half g_hh[N_NODES * HID];
__device__ __align__(16) float  g_q[N_NODES * HID];    // pre-scaled by invsqrtC*log2e
__device__ __align__(16) float  g_skip[N_NODES * HID];
// interleaved kv: per node, lane L (0..31) owns halves {k[2L],k[2L+1],v[2L],v[2L+1]}
__device__ __align__(16) __half g_kv[N_NODES * 128];
__device__ __align__(16) __half g_wt[13 * 64 * 72];
__device__ int   g_cnt[N_NODES];
__device__ int   g_rowptr[N_NODES + 1];
__device__ int   g_fill[N_NODES];
__device__ ull   g_edge[N_EDGES];                      // (ea<<32 | src*256)  [byte offset]
__device__ int   g_psum[64];
__device__ int   g_scan_ctr;

// ================= device bodies =============================================

__device__ __forceinline__ void ingemm_body(int bid, int t,
                         const float* __restrict__ x,
                         const float* __restrict__ Win,
                         const float* __restrict__ b_in,
                         float* xs) {
    int c = t & 63, rg = t >> 6;
    ull w2[26];
    #pragma unroll
    for (int k = 0; k < 25; k++)
        w2[k] = packf2(Win[(2 * k) * HID + c], Win[(2 * k + 1) * HID + c]);
    w2[25] = 0ull;
    int n0 = bid * 64;
    for (int idx = t; idx < 64 * IN_DIM; idx += 256) {
        int r = idx / IN_DIM, k = idx % IN_DIM;
        int row = n0 + r;
        xs[r * 52 + k] = (row < N_NODES) ? x[row * IN_DIM + k] : 0.f;
    }
    if (rg == 0) { xs[c * 52 + 50] = 0.f; xs[c * 52 + 51] = 0.f; }
    __syncthreads();
    float bias = b_in[c];
    int rend = min(rg * 16 + 16, N_NODES - n0);
    for (int r = rg * 16; r < rend; r++) {
        const ulonglong2* hr = (const ulonglong2*)&xs[r * 52];
        ull acc_a = packf2(bias, 0.f), acc_b = 0ull;
        #pragma unroll
        for (int kk = 0; kk < 13; kk++) {
            ulonglong2 hv = hr[kk];
            acc_a = ff2(w2[2 * kk + 0], hv.x, acc_a);
            acc_b = ff2(w2[2 * kk + 1], hv.y, acc_b);
        }
        float acc = sum2(acc_a) + sum2(acc_b);
        g_h[(n0 + r) * HID + c] = acc;
        g_hh[(n0 + r) * HID + c] = __float2half_rn(acc);
    }
}

__device__ __forceinline__ void prepw_body(int id,
                         const float* __restrict__ Wq, const float* __restrict__ Wk,
                         const float* __restrict__ Wv, const float* __restrict__ Wsk,
                         const float* __restrict__ Wc1) {
    if (id >= 13 * 4096) return;
    int k = id & 63, n = (id >> 6) & 63, m = id >> 12;
    const float* W;
    float scal = 1.f;
    if (m == 12) W = Wc1;
    else {
        int li = m >> 2, mat = m & 3;
        if (mat == 0)      { W = Wq + li * 4096; scal = INV_SQRT_C * LOG2E; }
        else if (mat == 1) W = Wk  + li * 4096;
        else if (mat == 2) W = Wv  + li * 4096;
        else               W = Wsk + li * 4096;
    }
    g_wt[(m * 64 + n) * 72 + k] = __float2half_rn(W[k * 64 + n] * scal);
}

__device__ __forceinline__ void gemm4_body(int li, int t, int tile_start, int tile_stride,
                        const float* __restrict__ bq, const float* __restrict__ bk,
                        const float* __restrict__ bv, const float* __restrict__ bsk) {
    __shared__ __half As[64][72];
    __shared__ __half Bs[4][64][72];
    __shared__ float  bias_s[4][64];

    int w = t >> 5, lane = t & 31;
    int mat = w & 3, rg = w >> 2;

    const float* b;
    if (mat == 0)      b = bq  + li * 64;
    else if (mat == 1) b = bk  + li * 64;
    else if (mat == 2) b = bv  + li * 64;
    else               b = bsk + li * 64;
    float scal = (mat == 0) ? INV_SQRT_C * LOG2E : 1.f;

    {
        const uint4* src = (const uint4*)(g_wt + (li * 4 + mat) * 64 * 72);
        uint4* dst = (uint4*)&Bs[mat][0][0];
        for (int idx = rg * 32 + lane; idx < 576; idx += 128)
            dst[idx] = src[idx];
        if (rg == 0)
            for (int c = lane; c < 64; c += 32) bias_s[mat][c] = b[c] * scal;
    }

    int g = lane >> 2, tig = lane & 3;
    int r0 = rg * 16;
    int arow = t >> 3, acol = (t & 7) * 8;

    for (int tile = tile_start; tile < NTILES; tile += tile_stride) {
        int n0 = tile * 64;
        __syncthreads();
        {
            int row = n0 + arow;
            uint4 v = make_uint4(0u, 0u, 0u, 0u);
            if (row < N_NODES) v = *(const uint4*)&g_hh[row * 64 + acol];
            *(uint4*)&As[arow][acol] = v;
        }
        __syncthreads();

        unsigned afr[4][4];
        #pragma unroll
        for (int ks = 0; ks < 4; ks++) {
            int k0 = ks * 16;
            afr[ks][0] = *(const unsigned*)&As[r0 + g][k0 + 2 * tig];
            afr[ks][1] = *(const unsigned*)&As[r0 + g + 8][k0 + 2 * tig];
            afr[ks][2] = *(const unsigned*)&As[r0 + g][k0 + 2 * tig + 8];
            afr[ks][3] = *(const unsigned*)&As[r0 + g + 8][k0 + 2 * tig + 8];
        }

        int row0 = n0 + r0 + g;
        int row1 = row0 + 8;

        #pragma unroll
        for (int nt = 0; nt < 8; nt++) {
            int col = nt * 8 + 2 * tig;
            float c0 = bias_s[mat][col], c1 = bias_s[mat][col + 1];
            float c2 = c0, c3 = c1;
            #pragma unroll
            for (int ks = 0; ks < 4; ks++) {
                unsigned b0 = *(const unsigned*)&Bs[mat][nt * 8 + g][ks * 16 + 2 * tig];
                unsigned b1 = *(const unsigned*)&Bs[mat][nt * 8 + g][ks * 16 + 2 * tig + 8];
                asm volatile(
                    "mma.sync.aligned.m16n8k16.row.col.f32.f16.f16.f32 "
                    "{%0,%1,%2,%3}, {%4,%5,%6,%7}, {%8,%9}, {%0,%1,%2,%3};"
                    : "+f"(c0), "+f"(c1), "+f"(c2), "+f"(c3)
                    : "r"(afr[ks][0]), "r"(afr[ks][1]), "r"(afr[ks][2]), "r"(afr[ks][3]),
                      "r"(b0), "r"(b1));
            }
            if (mat == 0) {
                if (row0 < N_NODES) *(float2*)&g_q[row0 * 64 + col] = make_float2(c0, c1);
                if (row1 < N_NODES) *(float2*)&g_q[row1 * 64 + col] = make_float2(c2, c3);
            } else if (mat == 3) {
                if (row0 < N_NODES) *(float2*)&g_skip[row0 * 64 + col] = make_float2(c0, c1);
                if (row1 < N_NODES) *(float2*)&g_skip[row1 * 64 + col] = make_float2(c2, c3);
            } else {
                // interleaved: channels (col,col+1) -> halves (col>>1)*4 + {0,1}(k) / {2,3}(v)
                int pos = ((col >> 1) << 2) + ((mat == 2) ? 2 : 0);
                if (row0 < N_NODES) *(__half2*)&g_kv[row0 * 128 + pos] = __floats2half2_rn(c0, c1);
                if (row1 < N_NODES) *(__half2*)&g_kv[row1 * 128 + pos] = __floats2half2_rn(c2, c3);
            }
        }
    }
}

__device__ __forceinline__ void scatter_body(int e, const int* __restrict__ ei,
                                             const float* __restrict__ ea) {
    if (e < N_EDGES) {
        int dst = ei[N_EDGES + e];
        int base = g_rowptr[dst] + g_psum[dst >> 10];
        int pos = base + atomicAdd(&g_fill[dst], 1);
        // store BYTE offset of the kv row (src*256) in the low word
        g_edge[pos] = ((ull)__float_as_uint(ea[e]) << 32) | ((unsigned)ei[e] << 8);
    }
}

// ================= kernels ===================================================

__global__ __launch_bounds__(256) void k_fused1(
        const float* __restrict__ x, const float* __restrict__ Win,
        const float* __restrict__ b_in,
        const float* __restrict__ Wq, const float* __restrict__ Wk,
        const float* __restrict__ Wv, const float* __restrict__ Wsk,
        const float* __restrict__ Wc1,
        const int* __restrict__ ei) {
    __shared__ __align__(16) float xs[64 * 52];
    int b = blockIdx.x, t = threadIdx.x;
    if (b < NTILES) {
        ingemm_body(b, t, x, Win, b_in, xs);
    } else if (b < NTILES + PREPW_BLK) {
        prepw_body((b - NTILES) * 256 + t, Wq, Wk, Wv, Wsk, Wc1);
    } else {
        int e = (b - NTILES - PREPW_BLK) * 256 + t;
        if (e < N_NODES) g_fill[e] = 0;
        if (e < N_EDGES) atomicAdd(&g_cnt[ei[N_EDGES + e]], 1);
    }
}

__global__ void k_scan() {
    __shared__ int wsum[32];
    __shared__ int s_last;
    __shared__ int w0tot;
    int t = threadIdx.x, lane = t & 31, wid = t >> 5;
    int i = blockIdx.x * 1024 + t;
    int v = (i < N_NODES) ? g_cnt[i] : 0;
    if (i < N_NODES) g_cnt[i] = 0;
    int incl = v;
    #pragma unroll
    for (int o = 1; o < 32; o <<= 1) {
        int u = __shfl_up_sync(0xffffffffu, incl, o);
        if (lane >= o) incl += u;
    }
    if (lane == 31) wsum[wid] = incl;
    __syncthreads();
    if (wid == 0) {
        int ws = wsum[lane];
        int wincl = ws;
        #pragma unroll
        for (int o = 1; o < 32; o <<= 1) {
            int u = __shfl_up_sync(0xffffffffu, wincl, o);
            if (lane >= o) wincl += u;
        }
        wsum[lane] = wincl - ws;
        if (lane == 31) g_psum[blockIdx.x] = wincl;
    }
    __syncthreads();
    int excl = incl - v + wsum[wid];
    if (i < N_NODES) g_rowptr[i] = excl;

    __threadfence();
    if (t == 0) s_last = (atomicAdd(&g_scan_ctr, 1) == SCAN_BLK - 1) ? 1 : 0;
    __syncthreads();
    if (s_last) {
        int v2 = (t < SCAN_BLK) ? *((volatile int*)g_psum + t) : 0;
        int incl2 = v2;
        if (t < 64) {
            #pragma unroll
            for (int o = 1; o < 32; o <<= 1) {
                int u = __shfl_up_sync(0xffffffffu, incl2, o);
                if (lane >= o) incl2 += u;
            }
            if (t == 31) w0tot = incl2;
        }
        __syncthreads();
        if (t < 64) {
            int excl2 = incl2 - v2 + ((t >= 32) ? w0tot : 0);
            if (t < SCAN_BLK) g_psum[t] = excl2;
            if (t == SCAN_BLK - 1) g_rowptr[N_NODES] = v2;
        }
        if (t == 0) g_scan_ctr = 0;
    }
}

__global__ __launch_bounds__(512) void k_gemm4sc(int li,
                        const float* __restrict__ bq, const float* __restrict__ bk,
                        const float* __restrict__ bv, const float* __restrict__ bsk,
                        const int* __restrict__ ei, const float* __restrict__ ea) {
    if (blockIdx.x < G4_BLOCKS) {
        gemm4_body(li, threadIdx.x, blockIdx.x, G4_BLOCKS, bq, bk, bv, bsk);
    } else {
        int e = (blockIdx.x - G4_BLOCKS) * 512 + threadIdx.x;
        scatter_body(e, ei, ea);
    }
}

__global__ __launch_bounds__(512) void k_gemm4(int li,
                        const float* __restrict__ bq, const float* __restrict__ bk,
                        const float* __restrict__ bv, const float* __restrict__ bsk) {
    gemm4_body(li, threadIdx.x, blockIdx.x, G4_BLOCKS, bq, bk, bv, bsk);
}

// ---------------- fused node kernel: warp/node, 64-thr blocks, depth-4 -------
// edge word low 32 bits = byte offset of kv row; lane offset precomputed
#define LDKV(E) __ldg((const uint2*)(kvb + (unsigned)(E)))
#define NODE_BODY(E, R) { \
    float w_ = __uint_as_float((unsigned)((E) >> 32)); \
    float2 kf_ = __half22float2(*(const __half2*)&(R).x); \
    float2 vf_ = __half22float2(*(const __half2*)&(R).y); \
    float p_ = q2.x * kf_.x + q2.y * kf_.y; \
    p_ += __shfl_xor_sync(0xffffffffu, p_, 1, 8); \
    p_ += __shfl_xor_sync(0xffffffffu, p_, 2, 8); \
    p_ += __shfl_xor_sync(0xffffffffu, p_, 4, 8); \
    float ex_ = exp2f(fmaf(w_, qwe, p_)); \
    d += ex_; spw = fmaf(ex_, w_, spw); \
    accx = fmaf(ex_, vf_.x, accx); accy = fmaf(ex_, vf_.y, accy); \
}

__global__ __launch_bounds__(64) void k_node3(int li,
                        const float* __restrict__ Wedge,
                        const float* __restrict__ Wbeta,
                        const float* __restrict__ lng,
                        const float* __restrict__ lnb) {
    int n = blockIdx.x * 2 + (threadIdx.x >> 5);
    if (n >= N_NODES) return;
    int lane = threadIdx.x & 31;
    const char* kvb = (const char*)g_kv + lane * 8;   // per-lane base

    float2 q2  = ((const float2*)g_q)[n * 32 + lane];     // pre-scaled (invsqrtC*log2e)
    float2 we2 = ((const float2*)Wedge)[li * 32 + lane];

    float pw = q2.x * we2.x + q2.y * we2.y;
    pw += __shfl_xor_sync(0xffffffffu, pw, 1, 8);
    pw += __shfl_xor_sync(0xffffffffu, pw, 2, 8);
    pw += __shfl_xor_sync(0xffffffffu, pw, 4, 8);
    float qwe = pw;                                       // log2e-scaled

    int j0 = g_rowptr[n] + g_psum[n >> 10];
    int j1 = g_rowptr[n + 1] + g_psum[(n + 1) >> 10];
    int cnt = j1 - j0;
    const ull* ep = g_edge + j0;

    float d = 0.f, spw = 0.f, accx = 0.f, accy = 0.f;

    ull e0 = 0, e1 = 0, e2 = 0, e3 = 0;
    uint2 r0 = make_uint2(0u,0u), r1 = r0, r2 = r0, r3 = r0;
    if (cnt > 0) { e0 = __ldg(ep + 0); r0 = LDKV(e0); }
    if (cnt > 1) { e1 = __ldg(ep + 1); r1 = LDKV(e1); }
    if (cnt > 2) { e2 = __ldg(ep + 2); r2 = LDKV(e2); }
    if (cnt > 3) { e3 = __ldg(ep + 3); r3 = LDKV(e3); }

    int j = 0;
    for (; j + 8 <= cnt; j += 4) {
        NODE_BODY(e0, r0); e0 = __ldg(ep + j + 4); r0 = LDKV(e0);
        NODE_BODY(e1, r1); e1 = __ldg(ep + j + 5); r1 = LDKV(e1);
        NODE_BODY(e2, r2); e2 = __ldg(ep + j + 6); r2 = LDKV(e2);
        NODE_BODY(e3, r3); e3 = __ldg(ep + j + 7); r3 = LDKV(e3);
    }
    int left = cnt - j;
    if (left > 0) NODE_BODY(e0, r0);
    if (left > 1) NODE_BODY(e1, r1);
    if (left > 2) NODE_BODY(e2, r2);
    if (left > 3) NODE_BODY(e3, r3);
    for (int jj = j + 4; jj < cnt; jj++) {
        ull e = __ldg(ep + jj); uint2 r = LDKV(e);
        NODE_BODY(e, r);
    }

    float inv = 1.f / (d + 1e-16f);
    float ox = (accx + we2.x * spw) * inv;
    float oy = (accy + we2.y * spw) * inv;

    float2 xr = ((const float2*)g_skip)[n * 32 + lane];
    const float2* Wb = (const float2*)(Wbeta + li * 192);
    float2 w1 = Wb[lane], w2 = Wb[32 + lane], w3 = Wb[64 + lane];
    float contrib = ox * w1.x + oy * w1.y + xr.x * w2.x + xr.y * w2.y
                  + (ox - xr.x) * w3.x + (oy - xr.y) * w3.y;
    #pragma unroll
    for (int o = 16; o >= 1; o >>= 1)
        contrib += __shfl_xor_sync(0xffffffffu, contrib, o);
    float beta = 1.f / (1.f + __expf(-contrib));

    float2 hres = ((const float2*)g_h)[n * 32 + lane];
    float zx = fmaf(beta, xr.x - ox, ox) + hres.x;
    float zy = fmaf(beta, xr.y - oy, oy) + hres.y;

    float s1 = zx + zy;
    float s2 = zx * zx + zy * zy;
    #pragma unroll
    for (int o = 16; o >= 1; o >>= 1) {
        s1 += __shfl_xor_sync(0xffffffffu, s1, o);
        s2 += __shfl_xor_sync(0xffffffffu, s2, o);
    }
    float mu  = s1 * (1.f / 64.f);
    float var = s2 * (1.f / 64.f) - mu * mu;
    float rstd = rsqrtf(var + LN_EPS);
    float2 g = ((const float2*)lng)[li * 32 + lane];
    float2 b = ((const float2*)lnb)[li * 32 + lane];
    float hx = (zx - mu) * rstd * g.x + b.x;
    float hy = (zy - mu) * rstd * g.y + b.y;
    ((float2*)g_h)[n * 32 + lane] = make_float2(hx, hy);
    __half2 hh = __floats2half2_rn(hx, hy);
    ((unsigned*)g_hh)[n * 32 + lane] = *(unsigned*)&hh;
}

// ---------------- head: stage1 HMMA + stage2 FFMA2 ---------------------------
__global__ __launch_bounds__(256) void k_final(const float* __restrict__ bc1,
                        const float* __restrict__ Wc2, const float* __restrict__ bc2,
                        float* __restrict__ out) {
    __shared__ __half As[64][72];
    __shared__ __half Bs[64][72];
    __shared__ __align__(16) float h1s[64 * 64];
    __shared__ float bias1[64];

    int t = threadIdx.x;
    int w = t >> 5, lane = t & 31;
    int n0 = blockIdx.x * 64;

    for (int idx = t; idx < 512; idx += 256) {
        int row = n0 + (idx >> 3), col = (idx & 7) * 8;
        uint4 v = make_uint4(0u, 0u, 0u, 0u);
        if (row < N_NODES) v = *(const uint4*)&g_hh[row * 64 + col];
        *(uint4*)&As[idx >> 3][col] = v;
    }
    {
        const uint4* src = (const uint4*)(g_wt + 12 * 64 * 72);
        uint4* dst = (uint4*)&Bs[0][0];
        for (int idx = t; idx < 576; idx += 256) dst[idx] = src[idx];
    }
    if (t < 64) bias1[t] = bc1[t];
    __syncthreads();

    {
        int rg = w & 3, nh = w >> 2;
        int g = lane >> 2, tig = lane & 3;
        int r0 = rg * 16;
        unsigned afr[4][4];
        #pragma unroll
        for (int ks = 0; ks < 4; ks++) {
            int k0 = ks * 16;
            afr[ks][0] = *(const unsigned*)&As[r0 + g][k0 + 2 * tig];
            afr[ks][1] = *(const unsigned*)&As[r0 + g + 8][k0 + 2 * tig];
            afr[ks][2] = *(const unsigned*)&As[r0 + g][k0 + 2 * tig + 8];
            afr[ks][3] = *(const unsigned*)&As[r0 + g + 8][k0 + 2 * tig + 8];
        }
        #pragma unroll
        for (int q = 0; q < 4; q++) {
            int nt = nh * 4 + q;
            int col = nt * 8 + 2 * tig;
            float c0 = bias1[col], c1 = bias1[col + 1];
            float c2 = c0, c3 = c1;
            #pragma unroll
            for (int ks = 0; ks < 4; ks++) {
                unsigned b0 = *(const unsigned*)&Bs[nt * 8 + g][ks * 16 + 2 * tig];
                unsigned b1 = *(const unsigned*)&Bs[nt * 8 + g][ks * 16 + 2 * tig + 8];
                asm volatile(
                    "mma.sync.aligned.m16n8k16.row.col.f32.f16.f16.f32 "
                    "{%0,%1,%2,%3}, {%4,%5,%6,%7}, {%8,%9}, {%0,%1,%2,%3};"
                    : "+f"(c0), "+f"(c1), "+f"(c2), "+f"(c3)
                    : "r"(afr[ks][0]), "r"(afr[ks][1]), "r"(afr[ks][2]), "r"(afr[ks][3]),
                      "r"(b0), "r"(b1));
            }
            *(float2*)&h1s[(r0 + g) * 64 + col]     = make_float2(fmaxf(c0, 0.f), fmaxf(c1, 0.f));
            *(float2*)&h1s[(r0 + g + 8) * 64 + col] = make_float2(fmaxf(c2, 0.f), fmaxf(c3, 0.f));
        }
    }
    __syncthreads();

    if (t < 240) {
        int c2 = t % 12, rg2 = t / 12;
        ull wr2[32];
        #pragma unroll
        for (int k = 0; k < 32; k++)
            wr2[k] = packf2(Wc2[(2 * k) * NC + c2], Wc2[(2 * k + 1) * NC + c2]);
        float b2 = bc2[c2];
        int rmax = min(64, N_NODES - n0);
        for (int r = rg2; r < rmax; r += 20) {
            const ulonglong2* hr = (const ulonglong2*)&h1s[r * 64];
            ull acc_a = packf2(b2, 0.f), acc_b = 0ull;
            #pragma unroll
            for (int kk = 0; kk < 16; kk++) {
                ulonglong2 hv = hr[kk];
                acc_a = ff2(wr2[2 * kk + 0], hv.x, acc_a);
                acc_b = ff2(wr2[2 * kk + 1], hv.y, acc_b);
            }
            out[(n0 + r) * NC + c2] = sum2(acc_a) + sum2(acc_b);
        }
    }
}

// ---------------- launch -----------------------------------------------------
extern "C" void kernel_launch(void* const* d_in, const int* in_sizes, int n_in,
                              void* d_out, int out_size) {
    const float* x     = (const float*)d_in[0];
    const int*   ei    = (const int*)  d_in[1];
    const float* ea    = (const float*)d_in[2];
    const float* Win   = (const float*)d_in[3];
    const float* b_in  = (const float*)d_in[4];
    const float* Wq    = (const float*)d_in[5];
    const float* bq    = (const float*)d_in[6];
    const float* Wk    = (const float*)d_in[7];
    const float* bk    = (const float*)d_in[8];
    const float* Wv    = (const float*)d_in[9];
    const float* bv    = (const float*)d_in[10];
    const float* Wedge = (const float*)d_in[11];
    const float* Wskip = (const float*)d_in[12];
    const float* bskip = (const float*)d_in[13];
    const float* Wbeta = (const float*)d_in[14];
    const float* ln_g  = (const float*)d_in[15];
    const float* ln_b  = (const float*)d_in[16];
    const float* Wc1   = (const float*)d_in[17];
    const float* bc1   = (const float*)d_in[18];
    const float* Wc2   = (const float*)d_in[19];
    const float* bc2   = (const float*)d_in[20];
    float* out = (float*)d_out;

    int nodeblk = (N_NODES + 1) / 2;     // 2 warps per block

    // launch #4 (ncu capture slot) = k_node3 layer 0
    k_fused1<<<NTILES + PREPW_BLK + HIST_BLK, 256>>>(x, Win, b_in,
                Wq, Wk, Wv, Wskip, Wc1, ei);                                // 1
    k_scan<<<SCAN_BLK, 1024>>>();                                           // 2
    k_gemm4sc<<<G4_BLOCKS + SCAT_BLK, 512>>>(0, bq, bk, bv, bskip, ei, ea); // 3
    k_node3<<<nodeblk, 64>>>(0, Wedge, Wbeta, ln_g, ln_b);                  // 4 (profiled)

    for (int li = 1; li < NLAYERS; li++) {
        k_gemm4<<<G4_BLOCKS, 512>>>(li, bq, bk, bv, bskip);
        k_node3<<<nodeblk, 64>>>(li, Wedge, Wbeta, ln_g, ln_b);
    }

    k_final<<<NTILES, 256>>>(bc1, Wc2, bc2, out);
}